// round 16
// baseline (speedup 1.0000x reference)
#include <cuda_runtime.h>
#include <cuda_fp16.h>
#include <math.h>

#define BB 8
#define TT 2048
#define EE 1024
#define HH 128
#define BT (BB*TT)

// ---------------- scratch (device globals: allocation-free) ----------------
__device__ float g_v[BT*HH];
__device__ float g_S[(size_t)BB*TT*TT];   // fp32 scores (read-only after score)
__device__ __half g_E[(size_t)BB*TT*TT];  // exp(S-cmax) fp16 (zero-init above diag)
__device__ float g_psum[16*BT];
__device__ unsigned g_cmaxu[BT];          // encoded column max (atomicMax)
__device__ float g_crcp[BT];              // 1/den
// fp16 hi/lo planes (pre-split operands)
__device__ __half g_xh[(size_t)BT*EE], g_xl[(size_t)BT*EE];
__device__ __half g_wth[3*HH*EE], g_wtl[3*HH*EE];   // W transposed [y][n][k]
__device__ __half g_qh[BT*HH], g_ql[BT*HH];
__device__ __half g_kh[BT*HH], g_kl[BT*HH];
__device__ __half g_vth[BT*HH];                     // (v*crcp)^T  [b][h][s]

// ---------------- helpers --------------------------------------------------
__device__ __forceinline__ unsigned fau(float x) { return __float_as_uint(x); }

// monotone float<->unsigned encoding for atomicMax
__device__ __forceinline__ unsigned fenc(float f) {
    unsigned u = __float_as_uint(f);
    return (u & 0x80000000u) ? ~u : (u | 0x80000000u);
}
__device__ __forceinline__ float fdec(unsigned e) {
    unsigned u = (e & 0x80000000u) ? (e & 0x7fffffffu) : ~e;
    return __uint_as_float(u);
}

__device__ __forceinline__ void mma16h(float c[4], const unsigned a[4], const unsigned b[2]) {
    asm volatile(
        "mma.sync.aligned.m16n8k16.row.col.f32.f16.f16.f32 "
        "{%0,%1,%2,%3}, {%4,%5,%6,%7}, {%8,%9}, {%0,%1,%2,%3};\n"
        : "+f"(c[0]), "+f"(c[1]), "+f"(c[2]), "+f"(c[3])
        : "r"(a[0]), "r"(a[1]), "r"(a[2]), "r"(a[3]), "r"(b[0]), "r"(b[1]));
}
__device__ __forceinline__ float ex2f(float y) {
    float e;
    asm("ex2.approx.f32 %0, %1;" : "=f"(e) : "f"(y));
    return e;
}
__device__ __forceinline__ void cp16(void* dst, const void* src) {
    unsigned d = (unsigned)__cvta_generic_to_shared(dst);
    asm volatile("cp.async.cg.shared.global [%0], [%1], 16;" :: "r"(d), "l"(src));
}
#define CP_COMMIT() asm volatile("cp.async.commit_group;")
#define CP_WAIT2()  asm volatile("cp.async.wait_group 2;")

__device__ __forceinline__ void ldsm4(unsigned r[4], const void* p) {
    unsigned a = (unsigned)__cvta_generic_to_shared(p);
    asm volatile("ldmatrix.sync.aligned.m8n8.x4.shared.b16 {%0,%1,%2,%3}, [%4];"
                 : "=r"(r[0]), "=r"(r[1]), "=r"(r[2]), "=r"(r[3]) : "r"(a));
}

// per-lane ldmatrix source address inside a swizzled [128][16]-half plane:
// logical word group lw (0 or 4) of row r lives at phys group lw ^ ((bit2 of r)<<2)
__device__ __forceinline__ const __half* smaddr(const __half (*p)[16], int row, int lw) {
    int w2 = lw ^ (((row >> 2) & 1) << 2);
    return &p[row][w2 * 2];
}

// ---------------- init: cmax accumulators to encoded -inf ------------------
__global__ void init_cmax() {
    g_cmaxu[blockIdx.x * 256 + threadIdx.x] = 0x007fffffu;  // fenc(-inf)
}

// ---------------- convert x -> fp16 hi/lo planes ---------------------------
__global__ void convert_x(const float* __restrict__ x) {
    size_t i = ((size_t)blockIdx.x * 256 + threadIdx.x) * 4;
    float4 v = *(const float4*)(x + i);
    __half h0 = __float2half_rn(v.x), h1 = __float2half_rn(v.y);
    __half h2 = __float2half_rn(v.z), h3 = __float2half_rn(v.w);
    __half2 hA = __halves2half2(h0, h1), hB = __halves2half2(h2, h3);
    __half2 lA = __halves2half2(__float2half_rn(v.x - __half2float(h0)),
                                __float2half_rn(v.y - __half2float(h1)));
    __half2 lB = __halves2half2(__float2half_rn(v.z - __half2float(h2)),
                                __float2half_rn(v.w - __half2float(h3)));
    *(__half2*)&g_xh[i]     = hA; *(__half2*)&g_xh[i + 2] = hB;
    *(__half2*)&g_xl[i]     = lA; *(__half2*)&g_xl[i + 2] = lB;
}

// ---------------- convert W -> transposed [n][k] fp16 hi/lo ----------------
__global__ void convert_wt(const float* __restrict__ Wk,
                           const float* __restrict__ Wq,
                           const float* __restrict__ Wv) {
    int y = blockIdx.y;
    const float* W = (y == 0) ? Wk : (y == 1) ? Wq : Wv;
    int idx = blockIdx.x * 256 + threadIdx.x;     // over HH*EE, k contiguous
    int n = idx / EE, k = idx % EE;
    float val = W[(size_t)k * HH + n];
    __half h = __float2half_rn(val);
    g_wth[(size_t)y * HH * EE + idx] = h;
    g_wtl[(size_t)y * HH * EE + idx] = __float2half_rn(val - __half2float(h));
}

// ---------------- K1: q/k/v = x @ W  (pure fp16 split GEMM, ldmatrix) ------
// tiles 128x128, k-chunk 16, 3-stage cp.async, swizzled fp16 hi/lo planes
__global__ void __launch_bounds__(256) qkv_kernel() {
    int y = blockIdx.y;
    const __half* wth = g_wth + (size_t)y * HH * EE;
    const __half* wtl = g_wtl + (size_t)y * HH * EE;

    __shared__ __half As[3][2][128][16];   // [stage][hi/lo][m][k16]  24KB
    __shared__ __half Bs[3][2][128][16];   // [stage][hi/lo][n][k16]  24KB

    int tid = threadIdx.x;
    int m0 = blockIdx.x * 128;
    int warp = tid >> 5, lane = tid & 31, g = lane >> 2, tq = lane & 3;
    int mbase = (warp >> 1) * 32, nbase = (warp & 1) * 64;
    int lrow = lane & 15, lw = (lane >> 4) * 4;    // ldmatrix lane source coords
    int ra = tid >> 1;
    int chA = ((tid & 1) ^ ((ra >> 2) & 1)) * 8;   // swizzled dst half-offset
    int srco = (tid & 1) * 8;

    float acc[2][8][4];
#pragma unroll
    for (int i = 0; i < 2; i++)
#pragma unroll
        for (int j = 0; j < 8; j++)
#pragma unroll
            for (int q = 0; q < 4; q++) acc[i][j][q] = 0.f;

    const int NC = EE / 16;
    auto ISSUE = [&](int c) {
        int st = c % 3, k0 = c * 16;
        cp16(&As[st][0][ra][chA], &g_xh[(size_t)(m0 + ra) * EE + k0 + srco]);
        cp16(&As[st][1][ra][chA], &g_xl[(size_t)(m0 + ra) * EE + k0 + srco]);
        cp16(&Bs[st][0][ra][chA], &wth[(size_t)ra * EE + k0 + srco]);
        cp16(&Bs[st][1][ra][chA], &wtl[(size_t)ra * EE + k0 + srco]);
        CP_COMMIT();
    };
    auto COMPUTE = [&](int st) {
        unsigned ahi[2][4], alo[2][4];
#pragma unroll
        for (int ma = 0; ma < 2; ma++) {
            int row = mbase + ma * 16 + lrow;
            ldsm4(ahi[ma], smaddr(As[st][0], row, lw));
            ldsm4(alo[ma], smaddr(As[st][1], row, lw));
        }
#pragma unroll
        for (int pair = 0; pair < 4; pair++) {
            int row = nbase + pair * 16 + lrow;
            unsigned thi[4], tlo[4];
            ldsm4(thi, smaddr(Bs[st][0], row, lw));
            ldsm4(tlo, smaddr(Bs[st][1], row, lw));
#pragma unroll
            for (int sub = 0; sub < 2; sub++) {
                unsigned bhi[2] = {thi[sub], thi[sub + 2]};
                unsigned blo[2] = {tlo[sub], tlo[sub + 2]};
                int nb = pair * 2 + sub;
#pragma unroll
                for (int ma = 0; ma < 2; ma++) {
                    mma16h(acc[ma][nb], ahi[ma], bhi);
                    mma16h(acc[ma][nb], ahi[ma], blo);
                    mma16h(acc[ma][nb], alo[ma], bhi);
                }
            }
        }
    };

    ISSUE(0); ISSUE(1); ISSUE(2);
    for (int c = 0; c < NC; c++) {
        CP_WAIT2();
        __syncthreads();
        COMPUTE(c % 3);
        __syncthreads();
        if (c + 3 < NC) ISSUE(c + 3); else CP_COMMIT();
    }

    // epilogue: v -> fp32; q,k -> fp16 hi/lo planes (their only consumer)
#pragma unroll
    for (int ma = 0; ma < 2; ma++)
#pragma unroll
        for (int nb = 0; nb < 8; nb++) {
            int r0 = m0 + mbase + ma * 16 + g;
            int cc = nbase + nb * 8 + 2 * tq;
            float v0 = acc[ma][nb][0], v1 = acc[ma][nb][1];
            float v2 = acc[ma][nb][2], v3 = acc[ma][nb][3];
            if (y == 2) {
                *(float2*)&g_v[(size_t)r0 * HH + cc]       = make_float2(v0, v1);
                *(float2*)&g_v[(size_t)(r0 + 8) * HH + cc] = make_float2(v2, v3);
            } else {
                __half* oh = (y == 0) ? g_kh : g_qh;
                __half* ol = (y == 0) ? g_kl : g_ql;
                __half h0 = __float2half_rn(v0), h1 = __float2half_rn(v1);
                __half h2 = __float2half_rn(v2), h3 = __float2half_rn(v3);
                *(__half2*)&oh[(size_t)r0 * HH + cc] = __halves2half2(h0, h1);
                *(__half2*)&ol[(size_t)r0 * HH + cc] =
                    __halves2half2(__float2half_rn(v0 - __half2float(h0)),
                                   __float2half_rn(v1 - __half2float(h1)));
                *(__half2*)&oh[(size_t)(r0 + 8) * HH + cc] = __halves2half2(h2, h3);
                *(__half2*)&ol[(size_t)(r0 + 8) * HH + cc] =
                    __halves2half2(__float2half_rn(v2 - __half2float(h2)),
                                   __float2half_rn(v3 - __half2float(h3)));
            }
        }
}

// ---------------- K2: S = sqrt(H)*q@k^T + fused colmax (fp16, ldmatrix) ----
__global__ void __launch_bounds__(256) score_kernel() {
    int bx = blockIdx.x, by = blockIdx.y;
    if (bx < by) return;                      // tile fully above diagonal
    int t0 = bx * 128, s0 = by * 128, b = blockIdx.z;

    __shared__ __half As[3][2][128][16];   // q hi/lo  [t][h16]
    __shared__ __half Bs[3][2][128][16];   // k hi/lo  [s][h16]

    const size_t qoff = (size_t)b * TT * HH;

    int tid = threadIdx.x;
    int warp = tid >> 5, lane = tid & 31, g = lane >> 2, tq = lane & 3;
    int mbase = (warp >> 1) * 32, nbase = (warp & 1) * 64;
    int lrow = lane & 15, lw = (lane >> 4) * 4;
    int ra = tid >> 1;
    int chA = ((tid & 1) ^ ((ra >> 2) & 1)) * 8;
    int srco = (tid & 1) * 8;

    float acc[2][8][4];
#pragma unroll
    for (int i = 0; i < 2; i++)
#pragma unroll
        for (int j = 0; j < 8; j++)
#pragma unroll
            for (int q = 0; q < 4; q++) acc[i][j][q] = 0.f;

    const int NC = HH / 16;
    auto ISSUE = [&](int c) {
        int st = c % 3, h0 = c * 16;
        cp16(&As[st][0][ra][chA], &g_qh[qoff + (size_t)(t0 + ra) * HH + h0 + srco]);
        cp16(&As[st][1][ra][chA], &g_ql[qoff + (size_t)(t0 + ra) * HH + h0 + srco]);
        cp16(&Bs[st][0][ra][chA], &g_kh[qoff + (size_t)(s0 + ra) * HH + h0 + srco]);
        cp16(&Bs[st][1][ra][chA], &g_kl[qoff + (size_t)(s0 + ra) * HH + h0 + srco]);
        CP_COMMIT();
    };
    auto COMPUTE = [&](int st) {
        unsigned ahi[2][4], alo[2][4];
#pragma unroll
        for (int ma = 0; ma < 2; ma++) {
            int row = mbase + ma * 16 + lrow;
            ldsm4(ahi[ma], smaddr(As[st][0], row, lw));
            ldsm4(alo[ma], smaddr(As[st][1], row, lw));
        }
#pragma unroll
        for (int pair = 0; pair < 4; pair++) {
            int row = nbase + pair * 16 + lrow;
            unsigned thi[4], tlo[4];
            ldsm4(thi, smaddr(Bs[st][0], row, lw));
            ldsm4(tlo, smaddr(Bs[st][1], row, lw));
#pragma unroll
            for (int sub = 0; sub < 2; sub++) {
                unsigned bhi[2] = {thi[sub], thi[sub + 2]};
                unsigned blo[2] = {tlo[sub], tlo[sub + 2]};
                int nb = pair * 2 + sub;
#pragma unroll
                for (int ma = 0; ma < 2; ma++) {
                    mma16h(acc[ma][nb], ahi[ma], bhi);
                    mma16h(acc[ma][nb], ahi[ma], blo);
                    mma16h(acc[ma][nb], alo[ma], bhi);
                }
            }
        }
    };

    ISSUE(0); ISSUE(1); ISSUE(2);
    for (int c = 0; c < NC; c++) {
        CP_WAIT2();
        __syncthreads();
        COMPUTE(c % 3);
        __syncthreads();
        if (c + 3 < NC) ISSUE(c + 3); else CP_COMMIT();
    }

    float* Sb = g_S + (size_t)b * TT * TT;
    const float scale = 11.31370849898476f;   // sqrt(128)
#pragma unroll
    for (int ma = 0; ma < 2; ma++)
#pragma unroll
        for (int nb = 0; nb < 8; nb++) {
            int r0 = t0 + mbase + ma * 16 + g;
            int cc = s0 + nbase + nb * 8 + 2 * tq;
            *(float2*)&Sb[(size_t)r0 * TT + cc] =
                make_float2(acc[ma][nb][0] * scale, acc[ma][nb][1] * scale);
            *(float2*)&Sb[(size_t)(r0 + 8) * TT + cc] =
                make_float2(acc[ma][nb][2] * scale, acc[ma][nb][3] * scale);
        }

    // fused per-column max over this tile (mask above-diagonal on diag tiles)
    bool diag = (bx == by);
#pragma unroll
    for (int nb = 0; nb < 8; nb++) {
#pragma unroll
        for (int p = 0; p < 2; p++) {
            int scol = nbase + nb * 8 + 2 * tq + p;   // local col in tile
            float m = -INFINITY;
#pragma unroll
            for (int ma = 0; ma < 2; ma++) {
#pragma unroll
                for (int rp = 0; rp < 2; rp++) {
                    int rrow = mbase + ma * 16 + g + rp * 8;
                    float v = acc[ma][nb][rp * 2 + p] * scale;
                    if (!diag || rrow >= scol) m = fmaxf(m, v);
                }
            }
            m = fmaxf(m, __shfl_xor_sync(0xffffffffu, m, 4));
            m = fmaxf(m, __shfl_xor_sync(0xffffffffu, m, 8));
            m = fmaxf(m, __shfl_xor_sync(0xffffffffu, m, 16));
            if (g == 0)
                atomicMax(&g_cmaxu[(size_t)b * TT + s0 + scol], fenc(m));
        }
    }
}

// -------- pass B: E = exp(S - cmax) -> fp16 plane + partial column sums ----
__global__ void expsum_partial() {
    int col = blockIdx.x * 256 + threadIdx.x;
    int b = col >> 11, s = col & 2047;
    int t0c = blockIdx.y * 128, t1c = t0c + 128;
    const float* Sb = g_S + (size_t)b * TT * TT;
    __half* Eb = g_E + (size_t)b * TT * TT;
    const float L = 1.4426950408889634f;
    float cml = fdec(g_cmaxu[col]) * L;

    // zero garbage above the diagonal inside this column's 128-block
    int z0 = s & ~127; if (z0 < t0c) z0 = t0c;
    int z1 = (s < t1c) ? s : t1c;
    for (int t = z0; t < z1; t++) Eb[(size_t)t * TT + s] = __ushort_as_half((unsigned short)0);

    float d0 = 0.f, d1 = 0.f, d2 = 0.f, d3 = 0.f;
    float d4 = 0.f, d5 = 0.f, d6 = 0.f, d7 = 0.f;
    int t = (s > t0c) ? s : t0c;
    for (; t + 7 < t1c; t += 8) {
        float v0 = __ldcs(&Sb[(size_t)t * TT + s]);
        float v1 = __ldcs(&Sb[(size_t)(t + 1) * TT + s]);
        float v2 = __ldcs(&Sb[(size_t)(t + 2) * TT + s]);
        float v3 = __ldcs(&Sb[(size_t)(t + 3) * TT + s]);
        float v4 = __ldcs(&Sb[(size_t)(t + 4) * TT + s]);
        float v5 = __ldcs(&Sb[(size_t)(t + 5) * TT + s]);
        float v6 = __ldcs(&Sb[(size_t)(t + 6) * TT + s]);
        float v7 = __ldcs(&Sb[(size_t)(t + 7) * TT + s]);
        float e0 = ex2f(fmaf(v0, L, -cml));
        float e1 = ex2f(fmaf(v1, L, -cml));
        float e2 = ex2f(fmaf(v2, L, -cml));
        float e3 = ex2f(fmaf(v3, L, -cml));
        float e4 = ex2f(fmaf(v4, L, -cml));
        float e5 = ex2f(fmaf(v5, L, -cml));
        float e6 = ex2f(fmaf(v6, L, -cml));
        float e7 = ex2f(fmaf(v7, L, -cml));
        Eb[(size_t)t * TT + s]       = __float2half_rn(e0);
        Eb[(size_t)(t + 1) * TT + s] = __float2half_rn(e1);
        Eb[(size_t)(t + 2) * TT + s] = __float2half_rn(e2);
        Eb[(size_t)(t + 3) * TT + s] = __float2half_rn(e3);
        Eb[(size_t)(t + 4) * TT + s] = __float2half_rn(e4);
        Eb[(size_t)(t + 5) * TT + s] = __float2half_rn(e5);
        Eb[(size_t)(t + 6) * TT + s] = __float2half_rn(e6);
        Eb[(size_t)(t + 7) * TT + s] = __float2half_rn(e7);
        d0 += e0; d1 += e1; d2 += e2; d3 += e3;
        d4 += e4; d5 += e5; d6 += e6; d7 += e7;
    }
    for (; t < t1c; t++) {
        float e = ex2f(fmaf(__ldcs(&Sb[(size_t)t * TT + s]), L, -cml));
        Eb[(size_t)t * TT + s] = __float2half_rn(e);
        d0 += e;
    }
    g_psum[blockIdx.y * BT + col] = ((d0 + d1) + (d2 + d3)) + ((d4 + d5) + (d6 + d7));
}

__global__ void den_combine() {
    int col = blockIdx.x * 256 + threadIdx.x;
    float d = 0.f;
#pragma unroll
    for (int c = 0; c < 16; c++) d += g_psum[c * BT + col];
    g_crcp[col] = 1.f / d;
}

// -------- v'^T: transpose v, fold crcp, to fp16 [b][h][s] ------------------
__global__ void scale_vt() {
    __shared__ float tile[32][33];
    int b = blockIdx.z;
    int s0 = blockIdx.x * 32, h0 = blockIdx.y * 32;
    int tx = threadIdx.x, ty = threadIdx.y;
    const float* vb = g_v + (size_t)b * TT * HH;
    const float* crcp = g_crcp + b * TT;
#pragma unroll
    for (int i = 0; i < 4; i++) {
        int s = s0 + ty + i * 8;
        tile[ty + i * 8][tx] = vb[(size_t)s * HH + h0 + tx] * crcp[s];
    }
    __syncthreads();
    __half* vtb = g_vth + (size_t)b * HH * TT;
#pragma unroll
    for (int i = 0; i < 4; i++) {
        int h = h0 + ty + i * 8;
        vtb[(size_t)h * TT + s0 + tx] = __float2half_rn(tile[tx][ty + i * 8]);
    }
}

// ---------------- K4: out = E @ v'  (fp16 k16 ldmatrix, 3-stage) -----------
__global__ void __launch_bounds__(256) out_kernel(float* __restrict__ outp) {
    int t0 = blockIdx.x * 128;
    int b  = blockIdx.y;

    __shared__ __half As[3][128][16];   // E  [t][s16]
    __shared__ __half Bs[3][128][16];   // v'^T [h][s16]

    const __half* Eb  = g_E  + (size_t)b * TT * TT;
    const __half* vtb = g_vth + (size_t)b * HH * TT;

    int tid = threadIdx.x;
    int warp = tid >> 5, lane = tid & 31, g = lane >> 2, tq = lane & 3;
    int mbase = (warp >> 1) * 32, nbase = (warp & 1) * 64;
    int lrow = lane & 15, lw = (lane >> 4) * 4;
    int ra = tid >> 1;
    int chA = ((tid & 1) ^ ((ra >> 2) & 1)) * 8;
    int srco = (tid & 1) * 8;

    float acc[2][8][4];
#pragma unroll
    for (int i = 0; i < 2; i++)
#pragma unroll
        for (int j = 0; j < 8; j++)
#pragma unroll
            for (int q = 0; q < 4; q++) acc[i][j][q] = 0.f;

    const int NC = t0 / 16 + 8;          // covers s < t0+128
    auto ISSUE = [&](int c) {
        int st = c % 3, s0c = c * 16;
        cp16(&As[st][ra][chA], &Eb[(size_t)(t0 + ra) * TT + s0c + srco]);
        cp16(&Bs[st][ra][chA], &vtb[(size_t)ra * TT + s0c + srco]);
        CP_COMMIT();
    };
    auto COMPUTE = [&](int st) {
        unsigned ah[2][4];
#pragma unroll
        for (int ma = 0; ma < 2; ma++) {
            int row = mbase + ma * 16 + lrow;
            ldsm4(ah[ma], smaddr(As[st], row, lw));
        }
#pragma unroll
        for (int pair = 0; pair < 4; pair++) {
            int row = nbase + pair * 16 + lrow;
            unsigned tb[4];
            ldsm4(tb, smaddr(Bs[st], row, lw));
#pragma unroll
            for (int sub = 0; sub < 2; sub++) {
                unsigned bh[2] = {tb[sub], tb[sub + 2]};
                int nb = pair * 2 + sub;
#pragma unroll
                for (int ma = 0; ma < 2; ma++) mma16h(acc[ma][nb], ah[ma], bh);
            }
        }
    };

    ISSUE(0); ISSUE(1); ISSUE(2);
    for (int c = 0; c < NC; c++) {
        CP_WAIT2();
        __syncthreads();
        COMPUTE(c % 3);
        __syncthreads();
        if (c + 3 < NC) ISSUE(c + 3); else CP_COMMIT();
    }

#pragma unroll
    for (int ma = 0; ma < 2; ma++)
#pragma unroll
        for (int nb = 0; nb < 8; nb++) {
            int r0 = t0 + mbase + ma * 16 + g;
            int cc = nbase + nb * 8 + 2 * tq;
            *(float2*)&outp[((size_t)b * TT + r0) * HH + cc] =
                make_float2(acc[ma][nb][0], acc[ma][nb][1]);
            *(float2*)&outp[((size_t)b * TT + r0 + 8) * HH + cc] =
                make_float2(acc[ma][nb][2], acc[ma][nb][3]);
        }
}

// ---------------------------------------------------------------------------
extern "C" void kernel_launch(void* const* d_in, const int* in_sizes, int n_in,
                              void* d_out, int out_size) {
    const float* x  = (const float*)d_in[0];
    const float* Wk = (const float*)d_in[1];
    const float* Wq = (const float*)d_in[2];
    const float* Wv = (const float*)d_in[3];
    float* out = (float*)d_out;

    init_cmax<<<BT / 256, 256>>>();                          // #1
    convert_x<<<(int)((size_t)BT * EE / 4 / 256), 256>>>(x); // #2
    convert_wt<<<dim3(HH * EE / 256, 3), 256>>>(Wk, Wq, Wv); // #3
    qkv_kernel<<<dim3(BT / 128, 3), 256>>>();                // #4 (ncu slot)
    score_kernel<<<dim3(TT / 128, TT / 128, BB), 256>>>();
    expsum_partial<<<dim3(BT / 256, 16), 256>>>();
    den_combine<<<BT / 256, 256>>>();
    scale_vt<<<dim3(TT / 32, HH / 32, BB), dim3(32, 8)>>>();
    out_kernel<<<dim3(TT / 128, BB), 256>>>(out);
}

// round 17
// speedup vs baseline: 1.5453x; 1.5453x over previous
#include <cuda_runtime.h>
#include <cuda_fp16.h>
#include <math.h>

#define BB 8
#define TT 2048
#define EE 1024
#define HH 128
#define BT (BB*TT)

// ---------------- scratch (device globals: allocation-free) ----------------
__device__ float g_v[BT*HH];
__device__ float g_S[(size_t)BB*TT*TT];   // fp32 scores (read-only after score)
__device__ __half g_E[(size_t)BB*TT*TT];  // exp(S-cmax) fp16 (zero-init above diag)
__device__ float g_psum[16*BT];
__device__ unsigned g_cmaxu[BT];          // encoded column max (atomicMax)
__device__ float g_crcp[BT];              // 1/den
// fp16 hi/lo planes (pre-split operands)
__device__ __half g_xh[(size_t)BT*EE], g_xl[(size_t)BT*EE];
__device__ __half g_wth[3*HH*EE], g_wtl[3*HH*EE];   // W transposed [y][n][k]
__device__ __half g_qh[BT*HH], g_ql[BT*HH];
__device__ __half g_kh[BT*HH], g_kl[BT*HH];
__device__ __half g_vth[BT*HH];                     // (v*crcp)^T  [b][h][s]

// ---------------- helpers --------------------------------------------------
__device__ __forceinline__ unsigned fau(float x) { return __float_as_uint(x); }

// monotone float<->unsigned encoding for atomicMax
__device__ __forceinline__ unsigned fenc(float f) {
    unsigned u = __float_as_uint(f);
    return (u & 0x80000000u) ? ~u : (u | 0x80000000u);
}
__device__ __forceinline__ float fdec(unsigned e) {
    unsigned u = (e & 0x80000000u) ? (e & 0x7fffffffu) : ~e;
    return __uint_as_float(u);
}

__device__ __forceinline__ void mma16h(float c[4], const unsigned a[4], const unsigned b[2]) {
    asm volatile(
        "mma.sync.aligned.m16n8k16.row.col.f32.f16.f16.f32 "
        "{%0,%1,%2,%3}, {%4,%5,%6,%7}, {%8,%9}, {%0,%1,%2,%3};\n"
        : "+f"(c[0]), "+f"(c[1]), "+f"(c[2]), "+f"(c[3])
        : "r"(a[0]), "r"(a[1]), "r"(a[2]), "r"(a[3]), "r"(b[0]), "r"(b[1]));
}
__device__ __forceinline__ float ex2f(float y) {
    float e;
    asm("ex2.approx.f32 %0, %1;" : "=f"(e) : "f"(y));
    return e;
}
__device__ __forceinline__ void cp16(void* dst, const void* src) {
    unsigned d = (unsigned)__cvta_generic_to_shared(dst);
    asm volatile("cp.async.cg.shared.global [%0], [%1], 16;" :: "r"(d), "l"(src));
}
#define CP_COMMIT() asm volatile("cp.async.commit_group;")
#define CP_WAIT1()  asm volatile("cp.async.wait_group 1;")

// swizzled 32-bit fragment load from a [128][16]-half plane
// logical word w (0..7) of row r lives at physical word w ^ ((bit2 of r)<<2)
__device__ __forceinline__ unsigned ldsw(const __half (*p)[16], int r, int w) {
    int w2 = w ^ (((r >> 2) & 1) << 2);
    return *(const unsigned*)&p[r][w2 * 2];
}

// ---------------- init: cmax accumulators to encoded -inf ------------------
__global__ void init_cmax() {
    g_cmaxu[blockIdx.x * 256 + threadIdx.x] = 0x007fffffu;  // fenc(-inf)
}

// ---------------- convert x -> fp16 hi/lo planes ---------------------------
__global__ void convert_x(const float* __restrict__ x) {
    size_t i = ((size_t)blockIdx.x * 256 + threadIdx.x) * 4;
    float4 v = *(const float4*)(x + i);
    __half h0 = __float2half_rn(v.x), h1 = __float2half_rn(v.y);
    __half h2 = __float2half_rn(v.z), h3 = __float2half_rn(v.w);
    __half2 hA = __halves2half2(h0, h1), hB = __halves2half2(h2, h3);
    __half2 lA = __halves2half2(__float2half_rn(v.x - __half2float(h0)),
                                __float2half_rn(v.y - __half2float(h1)));
    __half2 lB = __halves2half2(__float2half_rn(v.z - __half2float(h2)),
                                __float2half_rn(v.w - __half2float(h3)));
    *(__half2*)&g_xh[i]     = hA; *(__half2*)&g_xh[i + 2] = hB;
    *(__half2*)&g_xl[i]     = lA; *(__half2*)&g_xl[i + 2] = lB;
}

// ---------------- convert W -> transposed [n][k] fp16 hi/lo ----------------
__global__ void convert_wt(const float* __restrict__ Wk,
                           const float* __restrict__ Wq,
                           const float* __restrict__ Wv) {
    int y = blockIdx.y;
    const float* W = (y == 0) ? Wk : (y == 1) ? Wq : Wv;
    int idx = blockIdx.x * 256 + threadIdx.x;     // over HH*EE, k contiguous
    int n = idx / EE, k = idx % EE;
    float val = W[(size_t)k * HH + n];
    __half h = __float2half_rn(val);
    g_wth[(size_t)y * HH * EE + idx] = h;
    g_wtl[(size_t)y * HH * EE + idx] = __float2half_rn(val - __half2float(h));
}

// ---------------- K1: q/k/v = x @ W  (pure fp16 split GEMM) ----------------
// tiles 128x128, k-chunk 16, 3-stage cp.async issue-ahead-2, single barrier
__global__ void __launch_bounds__(256) qkv_kernel() {
    int y = blockIdx.y;
    const __half* wth = g_wth + (size_t)y * HH * EE;
    const __half* wtl = g_wtl + (size_t)y * HH * EE;

    __shared__ __half As[3][2][128][16];   // [stage][hi/lo][m][k16]  24KB
    __shared__ __half Bs[3][2][128][16];   // [stage][hi/lo][n][k16]  24KB

    int tid = threadIdx.x;
    int m0 = blockIdx.x * 128;
    int warp = tid >> 5, lane = tid & 31, g = lane >> 2, tq = lane & 3;
    int mbase = (warp >> 1) * 32, nbase = (warp & 1) * 64;
    int ra = tid >> 1;
    int chA = ((tid & 1) ^ ((ra >> 2) & 1)) * 8;   // swizzled dst half-offset
    int srco = (tid & 1) * 8;

    float acc[2][8][4];
#pragma unroll
    for (int i = 0; i < 2; i++)
#pragma unroll
        for (int j = 0; j < 8; j++)
#pragma unroll
            for (int q = 0; q < 4; q++) acc[i][j][q] = 0.f;

    const int NC = EE / 16;
    auto ISSUE = [&](int c) {
        int st = c % 3, k0 = c * 16;
        cp16(&As[st][0][ra][chA], &g_xh[(size_t)(m0 + ra) * EE + k0 + srco]);
        cp16(&As[st][1][ra][chA], &g_xl[(size_t)(m0 + ra) * EE + k0 + srco]);
        cp16(&Bs[st][0][ra][chA], &wth[(size_t)ra * EE + k0 + srco]);
        cp16(&Bs[st][1][ra][chA], &wtl[(size_t)ra * EE + k0 + srco]);
        CP_COMMIT();
    };
    auto COMPUTE = [&](int st) {
        unsigned ahi[2][4], alo[2][4];
#pragma unroll
        for (int ma = 0; ma < 2; ma++) {
            int r0 = mbase + ma * 16 + g;
            ahi[ma][0] = ldsw(As[st][0], r0, tq);     ahi[ma][1] = ldsw(As[st][0], r0 + 8, tq);
            ahi[ma][2] = ldsw(As[st][0], r0, tq + 4); ahi[ma][3] = ldsw(As[st][0], r0 + 8, tq + 4);
            alo[ma][0] = ldsw(As[st][1], r0, tq);     alo[ma][1] = ldsw(As[st][1], r0 + 8, tq);
            alo[ma][2] = ldsw(As[st][1], r0, tq + 4); alo[ma][3] = ldsw(As[st][1], r0 + 8, tq + 4);
        }
#pragma unroll
        for (int nb = 0; nb < 8; nb++) {
            int cc = nbase + nb * 8 + g;
            unsigned bhi[2], blo[2];
            bhi[0] = ldsw(Bs[st][0], cc, tq); bhi[1] = ldsw(Bs[st][0], cc, tq + 4);
            blo[0] = ldsw(Bs[st][1], cc, tq); blo[1] = ldsw(Bs[st][1], cc, tq + 4);
#pragma unroll
            for (int ma = 0; ma < 2; ma++) {
                mma16h(acc[ma][nb], ahi[ma], bhi);
                mma16h(acc[ma][nb], ahi[ma], blo);
                mma16h(acc[ma][nb], alo[ma], bhi);
            }
        }
    };

    ISSUE(0); ISSUE(1);
    for (int c = 0; c < NC; c++) {
        CP_WAIT1();
        __syncthreads();
        if (c + 2 < NC) ISSUE(c + 2); else CP_COMMIT();
        COMPUTE(c % 3);
    }

    // epilogue: v -> fp32; q,k -> fp16 hi/lo planes (their only consumer)
#pragma unroll
    for (int ma = 0; ma < 2; ma++)
#pragma unroll
        for (int nb = 0; nb < 8; nb++) {
            int r0 = m0 + mbase + ma * 16 + g;
            int cc = nbase + nb * 8 + 2 * tq;
            float v0 = acc[ma][nb][0], v1 = acc[ma][nb][1];
            float v2 = acc[ma][nb][2], v3 = acc[ma][nb][3];
            if (y == 2) {
                *(float2*)&g_v[(size_t)r0 * HH + cc]       = make_float2(v0, v1);
                *(float2*)&g_v[(size_t)(r0 + 8) * HH + cc] = make_float2(v2, v3);
            } else {
                __half* oh = (y == 0) ? g_kh : g_qh;
                __half* ol = (y == 0) ? g_kl : g_ql;
                __half h0 = __float2half_rn(v0), h1 = __float2half_rn(v1);
                __half h2 = __float2half_rn(v2), h3 = __float2half_rn(v3);
                *(__half2*)&oh[(size_t)r0 * HH + cc] = __halves2half2(h0, h1);
                *(__half2*)&ol[(size_t)r0 * HH + cc] =
                    __halves2half2(__float2half_rn(v0 - __half2float(h0)),
                                   __float2half_rn(v1 - __half2float(h1)));
                *(__half2*)&oh[(size_t)(r0 + 8) * HH + cc] = __halves2half2(h2, h3);
                *(__half2*)&ol[(size_t)(r0 + 8) * HH + cc] =
                    __halves2half2(__float2half_rn(v2 - __half2float(h2)),
                                   __float2half_rn(v3 - __half2float(h3)));
            }
        }
}

// ---------------- K2: S = sqrt(H)*q@k^T + fused colmax (pure fp16) ---------
__global__ void __launch_bounds__(256) score_kernel() {
    int bx = blockIdx.x, by = blockIdx.y;
    if (bx < by) return;                      // tile fully above diagonal
    int t0 = bx * 128, s0 = by * 128, b = blockIdx.z;

    __shared__ __half As[3][2][128][16];   // q hi/lo  [t][h16]
    __shared__ __half Bs[3][2][128][16];   // k hi/lo  [s][h16]

    const size_t qoff = (size_t)b * TT * HH;

    int tid = threadIdx.x;
    int warp = tid >> 5, lane = tid & 31, g = lane >> 2, tq = lane & 3;
    int mbase = (warp >> 1) * 32, nbase = (warp & 1) * 64;
    int ra = tid >> 1;
    int chA = ((tid & 1) ^ ((ra >> 2) & 1)) * 8;
    int srco = (tid & 1) * 8;

    float acc[2][8][4];
#pragma unroll
    for (int i = 0; i < 2; i++)
#pragma unroll
        for (int j = 0; j < 8; j++)
#pragma unroll
            for (int q = 0; q < 4; q++) acc[i][j][q] = 0.f;

    const int NC = HH / 16;
    auto ISSUE = [&](int c) {
        int st = c % 3, h0 = c * 16;
        cp16(&As[st][0][ra][chA], &g_qh[qoff + (size_t)(t0 + ra) * HH + h0 + srco]);
        cp16(&As[st][1][ra][chA], &g_ql[qoff + (size_t)(t0 + ra) * HH + h0 + srco]);
        cp16(&Bs[st][0][ra][chA], &g_kh[qoff + (size_t)(s0 + ra) * HH + h0 + srco]);
        cp16(&Bs[st][1][ra][chA], &g_kl[qoff + (size_t)(s0 + ra) * HH + h0 + srco]);
        CP_COMMIT();
    };
    auto COMPUTE = [&](int st) {
        unsigned ahi[2][4], alo[2][4];
#pragma unroll
        for (int ma = 0; ma < 2; ma++) {
            int r0 = mbase + ma * 16 + g;
            ahi[ma][0] = ldsw(As[st][0], r0, tq);     ahi[ma][1] = ldsw(As[st][0], r0 + 8, tq);
            ahi[ma][2] = ldsw(As[st][0], r0, tq + 4); ahi[ma][3] = ldsw(As[st][0], r0 + 8, tq + 4);
            alo[ma][0] = ldsw(As[st][1], r0, tq);     alo[ma][1] = ldsw(As[st][1], r0 + 8, tq);
            alo[ma][2] = ldsw(As[st][1], r0, tq + 4); alo[ma][3] = ldsw(As[st][1], r0 + 8, tq + 4);
        }
#pragma unroll
        for (int nb = 0; nb < 8; nb++) {
            int cc = nbase + nb * 8 + g;
            unsigned bhi[2], blo[2];
            bhi[0] = ldsw(Bs[st][0], cc, tq); bhi[1] = ldsw(Bs[st][0], cc, tq + 4);
            blo[0] = ldsw(Bs[st][1], cc, tq); blo[1] = ldsw(Bs[st][1], cc, tq + 4);
#pragma unroll
            for (int ma = 0; ma < 2; ma++) {
                mma16h(acc[ma][nb], ahi[ma], bhi);
                mma16h(acc[ma][nb], ahi[ma], blo);
                mma16h(acc[ma][nb], alo[ma], bhi);
            }
        }
    };

    ISSUE(0); ISSUE(1);
    for (int c = 0; c < NC; c++) {
        CP_WAIT1();
        __syncthreads();
        if (c + 2 < NC) ISSUE(c + 2); else CP_COMMIT();
        COMPUTE(c % 3);
    }

    float* Sb = g_S + (size_t)b * TT * TT;
    const float scale = 11.31370849898476f;   // sqrt(128)
#pragma unroll
    for (int ma = 0; ma < 2; ma++)
#pragma unroll
        for (int nb = 0; nb < 8; nb++) {
            int r0 = t0 + mbase + ma * 16 + g;
            int cc = s0 + nbase + nb * 8 + 2 * tq;
            *(float2*)&Sb[(size_t)r0 * TT + cc] =
                make_float2(acc[ma][nb][0] * scale, acc[ma][nb][1] * scale);
            *(float2*)&Sb[(size_t)(r0 + 8) * TT + cc] =
                make_float2(acc[ma][nb][2] * scale, acc[ma][nb][3] * scale);
        }

    // fused per-column max over this tile (mask above-diagonal on diag tiles)
    bool diag = (bx == by);
#pragma unroll
    for (int nb = 0; nb < 8; nb++) {
#pragma unroll
        for (int p = 0; p < 2; p++) {
            int scol = nbase + nb * 8 + 2 * tq + p;   // local col in tile
            float m = -INFINITY;
#pragma unroll
            for (int ma = 0; ma < 2; ma++) {
#pragma unroll
                for (int rp = 0; rp < 2; rp++) {
                    int rrow = mbase + ma * 16 + g + rp * 8;
                    float v = acc[ma][nb][rp * 2 + p] * scale;
                    if (!diag || rrow >= scol) m = fmaxf(m, v);
                }
            }
            m = fmaxf(m, __shfl_xor_sync(0xffffffffu, m, 4));
            m = fmaxf(m, __shfl_xor_sync(0xffffffffu, m, 8));
            m = fmaxf(m, __shfl_xor_sync(0xffffffffu, m, 16));
            if (g == 0)
                atomicMax(&g_cmaxu[(size_t)b * TT + s0 + scol], fenc(m));
        }
    }
}

// -------- pass B: E = exp(S - cmax) -> fp16 plane + partial column sums ----
__global__ void expsum_partial() {
    int col = blockIdx.x * 256 + threadIdx.x;
    int b = col >> 11, s = col & 2047;
    int t0c = blockIdx.y * 128, t1c = t0c + 128;
    const float* Sb = g_S + (size_t)b * TT * TT;
    __half* Eb = g_E + (size_t)b * TT * TT;
    const float L = 1.4426950408889634f;
    float cml = fdec(g_cmaxu[col]) * L;

    // zero garbage above the diagonal inside this column's 128-block
    int z0 = s & ~127; if (z0 < t0c) z0 = t0c;
    int z1 = (s < t1c) ? s : t1c;
    for (int t = z0; t < z1; t++) Eb[(size_t)t * TT + s] = __ushort_as_half((unsigned short)0);

    float d0 = 0.f, d1 = 0.f, d2 = 0.f, d3 = 0.f;
    float d4 = 0.f, d5 = 0.f, d6 = 0.f, d7 = 0.f;
    int t = (s > t0c) ? s : t0c;
    for (; t + 7 < t1c; t += 8) {
        float v0 = __ldcs(&Sb[(size_t)t * TT + s]);
        float v1 = __ldcs(&Sb[(size_t)(t + 1) * TT + s]);
        float v2 = __ldcs(&Sb[(size_t)(t + 2) * TT + s]);
        float v3 = __ldcs(&Sb[(size_t)(t + 3) * TT + s]);
        float v4 = __ldcs(&Sb[(size_t)(t + 4) * TT + s]);
        float v5 = __ldcs(&Sb[(size_t)(t + 5) * TT + s]);
        float v6 = __ldcs(&Sb[(size_t)(t + 6) * TT + s]);
        float v7 = __ldcs(&Sb[(size_t)(t + 7) * TT + s]);
        float e0 = ex2f(fmaf(v0, L, -cml));
        float e1 = ex2f(fmaf(v1, L, -cml));
        float e2 = ex2f(fmaf(v2, L, -cml));
        float e3 = ex2f(fmaf(v3, L, -cml));
        float e4 = ex2f(fmaf(v4, L, -cml));
        float e5 = ex2f(fmaf(v5, L, -cml));
        float e6 = ex2f(fmaf(v6, L, -cml));
        float e7 = ex2f(fmaf(v7, L, -cml));
        Eb[(size_t)t * TT + s]       = __float2half_rn(e0);
        Eb[(size_t)(t + 1) * TT + s] = __float2half_rn(e1);
        Eb[(size_t)(t + 2) * TT + s] = __float2half_rn(e2);
        Eb[(size_t)(t + 3) * TT + s] = __float2half_rn(e3);
        Eb[(size_t)(t + 4) * TT + s] = __float2half_rn(e4);
        Eb[(size_t)(t + 5) * TT + s] = __float2half_rn(e5);
        Eb[(size_t)(t + 6) * TT + s] = __float2half_rn(e6);
        Eb[(size_t)(t + 7) * TT + s] = __float2half_rn(e7);
        d0 += e0; d1 += e1; d2 += e2; d3 += e3;
        d4 += e4; d5 += e5; d6 += e6; d7 += e7;
    }
    for (; t < t1c; t++) {
        float e = ex2f(fmaf(__ldcs(&Sb[(size_t)t * TT + s]), L, -cml));
        Eb[(size_t)t * TT + s] = __float2half_rn(e);
        d0 += e;
    }
    g_psum[blockIdx.y * BT + col] = ((d0 + d1) + (d2 + d3)) + ((d4 + d5) + (d6 + d7));
}

__global__ void den_combine() {
    int col = blockIdx.x * 256 + threadIdx.x;
    float d = 0.f;
#pragma unroll
    for (int c = 0; c < 16; c++) d += g_psum[c * BT + col];
    g_crcp[col] = 1.f / d;
}

// -------- v'^T: transpose v, fold crcp, to fp16 [b][h][s] ------------------
__global__ void scale_vt() {
    __shared__ float tile[32][33];
    int b = blockIdx.z;
    int s0 = blockIdx.x * 32, h0 = blockIdx.y * 32;
    int tx = threadIdx.x, ty = threadIdx.y;
    const float* vb = g_v + (size_t)b * TT * HH;
    const float* crcp = g_crcp + b * TT;
#pragma unroll
    for (int i = 0; i < 4; i++) {
        int s = s0 + ty + i * 8;
        tile[ty + i * 8][tx] = vb[(size_t)s * HH + h0 + tx] * crcp[s];
    }
    __syncthreads();
    __half* vtb = g_vth + (size_t)b * HH * TT;
#pragma unroll
    for (int i = 0; i < 4; i++) {
        int h = h0 + ty + i * 8;
        vtb[(size_t)h * TT + s0 + tx] = __float2half_rn(tile[tx][ty + i * 8]);
    }
}

// ---------------- K4: out = E @ v'  (pure fp16 k16, 3-stage, 1 barrier) ----
__global__ void __launch_bounds__(256) out_kernel(float* __restrict__ outp) {
    int t0 = blockIdx.x * 128;
    int b  = blockIdx.y;

    __shared__ __half As[3][128][16];   // E  [t][s16]
    __shared__ __half Bs[3][128][16];   // v'^T [h][s16]

    const __half* Eb  = g_E  + (size_t)b * TT * TT;
    const __half* vtb = g_vth + (size_t)b * HH * TT;

    int tid = threadIdx.x;
    int warp = tid >> 5, lane = tid & 31, g = lane >> 2, tq = lane & 3;
    int mbase = (warp >> 1) * 32, nbase = (warp & 1) * 64;
    int ra = tid >> 1;
    int chA = ((tid & 1) ^ ((ra >> 2) & 1)) * 8;
    int srco = (tid & 1) * 8;

    float acc[2][8][4];
#pragma unroll
    for (int i = 0; i < 2; i++)
#pragma unroll
        for (int j = 0; j < 8; j++)
#pragma unroll
            for (int q = 0; q < 4; q++) acc[i][j][q] = 0.f;

    const int NC = t0 / 16 + 8;          // covers s < t0+128
    auto ISSUE = [&](int c) {
        int st = c % 3, s0c = c * 16;
        cp16(&As[st][ra][chA], &Eb[(size_t)(t0 + ra) * TT + s0c + srco]);
        cp16(&Bs[st][ra][chA], &vtb[(size_t)ra * TT + s0c + srco]);
        CP_COMMIT();
    };
    auto COMPUTE = [&](int st) {
        unsigned ah[2][4];
#pragma unroll
        for (int ma = 0; ma < 2; ma++) {
            int r0 = mbase + ma * 16 + g;
            ah[ma][0] = ldsw(As[st], r0, tq);     ah[ma][1] = ldsw(As[st], r0 + 8, tq);
            ah[ma][2] = ldsw(As[st], r0, tq + 4); ah[ma][3] = ldsw(As[st], r0 + 8, tq + 4);
        }
#pragma unroll
        for (int nb = 0; nb < 8; nb++) {
            int cc = nbase + nb * 8 + g;
            unsigned bh[2];
            bh[0] = ldsw(Bs[st], cc, tq); bh[1] = ldsw(Bs[st], cc, tq + 4);
#pragma unroll
            for (int ma = 0; ma < 2; ma++) mma16h(acc[ma][nb], ah[ma], bh);
        }
    };

    ISSUE(0); ISSUE(1);
    for (int c = 0; c < NC; c++) {
        CP_WAIT1();
        __syncthreads();
        if (c + 2 < NC) ISSUE(c + 2); else CP_COMMIT();
        COMPUTE(c % 3);
    }

#pragma unroll
    for (int ma = 0; ma < 2; ma++)
#pragma unroll
        for (int nb = 0; nb < 8; nb++) {
            int r0 = t0 + mbase + ma * 16 + g;
            int cc = nbase + nb * 8 + 2 * tq;
            *(float2*)&outp[((size_t)b * TT + r0) * HH + cc] =
                make_float2(acc[ma][nb][0], acc[ma][nb][1]);
            *(float2*)&outp[((size_t)b * TT + r0 + 8) * HH + cc] =
                make_float2(acc[ma][nb][2], acc[ma][nb][3]);
        }
}

// ---------------------------------------------------------------------------
extern "C" void kernel_launch(void* const* d_in, const int* in_sizes, int n_in,
                              void* d_out, int out_size) {
    const float* x  = (const float*)d_in[0];
    const float* Wk = (const float*)d_in[1];
    const float* Wq = (const float*)d_in[2];
    const float* Wv = (const float*)d_in[3];
    float* out = (float*)d_out;

    init_cmax<<<BT / 256, 256>>>();                          // #1
    convert_x<<<(int)((size_t)BT * EE / 4 / 256), 256>>>(x); // #2
    convert_wt<<<dim3(HH * EE / 256, 3), 256>>>(Wk, Wq, Wv); // #3
    qkv_kernel<<<dim3(BT / 128, 3), 256>>>();                // #4 (ncu slot)
    score_kernel<<<dim3(TT / 128, TT / 128, BB), 256>>>();
    expsum_partial<<<dim3(BT / 256, 16), 256>>>();
    den_combine<<<BT / 256, 256>>>();
    scale_vt<<<dim3(TT / 32, HH / 32, BB), dim3(32, 8)>>>();
    out_kernel<<<dim3(TT / 128, BB), 256>>>(out);
}